// round 2
// baseline (speedup 1.0000x reference)
#include <cuda_runtime.h>
#include <cstdint>

// Fixed problem geometry (B and NNZ derived from in_sizes at launch)
#define NMDIM 25
#define CDIM  64
#define NWDIM 55
#define MAX_NNZ 1024
#define ROWB (CDIM * 4)   // bytes per m-row in smem (64 ch * fp32)

// Per-nnz metadata, identical for all batch-blocks.
// off.x/.y/.z = BYTE offsets into unified smem [x1 | x2 | w]; off.w = M_out.
__device__ int4  g_off[MAX_NNZ];
__device__ float g_cg[MAX_NNZ];

__global__ void pack_idx_kernel(const int* __restrict__ M1,
                                const int* __restrict__ M2,
                                const int* __restrict__ l_ind,
                                const int* __restrict__ M_out,
                                const float* __restrict__ CG,
                                int nnz) {
    int n = blockIdx.x * blockDim.x + threadIdx.x;
    if (n < nnz) {
        int4 e;
        e.x = M1[n] * ROWB;
        e.y = NMDIM * ROWB + M2[n] * ROWB;
        e.z = 2 * NMDIM * ROWB + l_ind[n] * ROWB;
        e.w = M_out[n];
        g_off[n] = e;
        g_cg[n]  = CG[n];
    }
}

// ---- packed f32x2 helpers (PTX-only; ptxas never auto-fuses these) ----
__device__ __forceinline__ unsigned long long mul_f32x2(unsigned long long a,
                                                        unsigned long long b) {
    unsigned long long r;
    asm("mul.rn.f32x2 %0, %1, %2;" : "=l"(r) : "l"(a), "l"(b));
    return r;
}
__device__ __forceinline__ unsigned long long fma_f32x2(unsigned long long a,
                                                        unsigned long long b,
                                                        unsigned long long c) {
    unsigned long long r;
    asm("fma.rn.f32x2 %0, %1, %2, %3;" : "=l"(r) : "l"(a), "l"(b), "l"(c));
    return r;
}
__device__ __forceinline__ unsigned long long bcast_f32x2(float s) {
    unsigned long long r;
    asm("mov.b64 %0, {%1, %1};" : "=l"(r) : "f"(s));
    return r;
}

__global__ __launch_bounds__(32, 8)
void wtp_kernel(const float* __restrict__ x1,
                const float* __restrict__ x2,
                const float* __restrict__ w,
                float* __restrict__ out,
                int nnz) {
    // Unified smem: [x1: 25*64 | x2: 25*64 | w: 55*64] fp32 = 26880 B
    __shared__ __align__(16) float sm[(2 * NMDIM + NWDIM) * CDIM];

    const int b   = blockIdx.x;
    const int tid = threadIdx.x;   // thread t owns channels (2t, 2t+1)

    // ---- Stage this batch's operands into shared (float4, coalesced) ----
    {
        const float4* s1 = reinterpret_cast<const float4*>(x1 + (size_t)b * NMDIM * CDIM);
        const float4* s2 = reinterpret_cast<const float4*>(x2 + (size_t)b * NMDIM * CDIM);
        const float4* sw = reinterpret_cast<const float4*>(w  + (size_t)b * NWDIM * CDIM);
        float4* d = reinterpret_cast<float4*>(sm);
        const int N1  = NMDIM * CDIM / 4;   // 400
        const int NWq = NWDIM * CDIM / 4;   // 880
        for (int i = tid; i < N1; i += 32)  d[i]          = s1[i];
        for (int i = tid; i < N1; i += 32)  d[N1 + i]     = s2[i];
        for (int i = tid; i < NWq; i += 32) d[2 * N1 + i] = sw[i];
    }
    __syncthreads();

    // Per-thread base: dynamic index -> one IADD per operand (byte offsets).
    const char* base = reinterpret_cast<const char*>(sm) + tid * 8;
    char* outb = reinterpret_cast<char*>(out + (size_t)b * NMDIM * CDIM) + tid * 8;

    unsigned long long acc = 0ULL;   // packed float2 accumulator
    int cur = -1;                    // current output segment (M_out value)

    #pragma unroll 4
    for (int n = 0; n < nnz; ++n) {
        const int4  e  = g_off[n];     // uniform L1-hit broadcast
        const float cg = g_cg[n];

        // Segment change (M_out sorted): flush acc, zero-fill skipped rows.
        if (e.w != cur) {
            if (cur >= 0)
                *reinterpret_cast<unsigned long long*>(outb + cur * ROWB) = acc;
            for (int m = cur + 1; m < e.w; ++m)
                *reinterpret_cast<unsigned long long*>(outb + m * ROWB) = 0ULL;
            acc = 0ULL;
            cur = e.w;
        }

        const unsigned long long v1 =
            *reinterpret_cast<const unsigned long long*>(base + e.x);   // LDS.64
        const unsigned long long v2 =
            *reinterpret_cast<const unsigned long long*>(base + e.y);   // LDS.64
        const unsigned long long vw =
            *reinterpret_cast<const unsigned long long*>(base + e.z);   // LDS.64

        acc = fma_f32x2(mul_f32x2(v1, v2), mul_f32x2(vw, bcast_f32x2(cg)), acc);
    }

    // Tail flush + trailing zero rows (d_out is poisoned; write everything).
    if (cur >= 0)
        *reinterpret_cast<unsigned long long*>(outb + cur * ROWB) = acc;
    for (int m = cur + 1; m < NMDIM; ++m)
        *reinterpret_cast<unsigned long long*>(outb + m * ROWB) = 0ULL;
}

extern "C" void kernel_launch(void* const* d_in, const int* in_sizes, int n_in,
                              void* d_out, int out_size) {
    // metadata order == reference signature order:
    // x1, x2, weight, CG_vals, M_out, M1, M2, l_ind
    const float* x1    = (const float*)d_in[0];
    const float* x2    = (const float*)d_in[1];
    const float* wt    = (const float*)d_in[2];
    const float* cg    = (const float*)d_in[3];
    const int*   M_out = (const int*)d_in[4];
    const int*   M1    = (const int*)d_in[5];
    const int*   M2    = (const int*)d_in[6];
    const int*   l_ind = (const int*)d_in[7];

    const int nnz = in_sizes[3];
    const int B   = in_sizes[0] / (NMDIM * CDIM);

    pack_idx_kernel<<<(nnz + 255) / 256, 256>>>(M1, M2, l_ind, M_out, cg, nnz);
    wtp_kernel<<<B, 32>>>(x1, x2, wt, (float*)d_out, nnz);
}

// round 4
// speedup vs baseline: 3.1780x; 3.1780x over previous
#include <cuda_runtime.h>
#include <cstdint>

// Fixed problem geometry (B and NNZ derived from in_sizes at launch)
#define NMDIM 25
#define CDIM  64
#define NWDIM 55
#define MAX_NNZ 1024
#define ROWB (CDIM * 4)   // bytes per m-row in smem (64 ch * fp32)

// Per-nnz metadata, identical for all batch-blocks.
// e.x/.y/.z = BYTE offsets into unified smem [x1 | x2 | w]; e.w = CG bits.
__device__ int4 g_off[MAX_NNZ];
// Segment pointers over sorted M_out: segment m is [g_ptr[m], g_ptr[m+1]).
__device__ int  g_ptr[NMDIM + 1];

__global__ void pack_idx_kernel(const int* __restrict__ M1,
                                const int* __restrict__ M2,
                                const int* __restrict__ l_ind,
                                const int* __restrict__ M_out,
                                const float* __restrict__ CG,
                                int nnz) {
    int n = blockIdx.x * blockDim.x + threadIdx.x;
    if (n < nnz) {
        int4 e;
        e.x = M1[n] * ROWB;
        e.y = NMDIM * ROWB + M2[n] * ROWB;
        e.z = 2 * NMDIM * ROWB + l_ind[n] * ROWB;
        e.w = __float_as_int(CG[n]);
        g_off[n] = e;
    }
    // Segment boundaries via binary search (M_out sorted ascending).
    if (blockIdx.x == 0 && threadIdx.x <= NMDIM) {
        int m = threadIdx.x;
        int lo = 0, hi = nnz;
        while (lo < hi) {
            int mid = (lo + hi) >> 1;
            if (M_out[mid] < m) lo = mid + 1; else hi = mid;
        }
        g_ptr[m] = lo;
    }
}

// ---- packed f32x2 helpers (PTX-only; ptxas never auto-fuses these) ----
__device__ __forceinline__ unsigned long long mul_f32x2(unsigned long long a,
                                                        unsigned long long b) {
    unsigned long long r;
    asm("mul.rn.f32x2 %0, %1, %2;" : "=l"(r) : "l"(a), "l"(b));
    return r;
}
__device__ __forceinline__ unsigned long long fma_f32x2(unsigned long long a,
                                                        unsigned long long b,
                                                        unsigned long long c) {
    unsigned long long r;
    asm("fma.rn.f32x2 %0, %1, %2, %3;" : "=l"(r) : "l"(a), "l"(b), "l"(c));
    return r;
}
__device__ __forceinline__ unsigned long long bcast_f32x2(float s) {
    unsigned long long r;
    asm("mov.b64 %0, {%1, %1};" : "=l"(r) : "f"(s));
    return r;
}

__global__ __launch_bounds__(128, 8)
void wtp_kernel(const float* __restrict__ x1,
                const float* __restrict__ x2,
                const float* __restrict__ w,
                float* __restrict__ out,
                int nnz) {
    // Unified smem: [x1: 25*64 | x2: 25*64 | w: 55*64] fp32 = 26880 B
    __shared__ __align__(16) float sm[(2 * NMDIM + NWDIM) * CDIM];

    const int b   = blockIdx.x;
    const int tid = threadIdx.x;
    const int lid = tid & 31;   // lane: owns channels (2*lid, 2*lid+1)
    const int wid = tid >> 5;   // warp 0..3: handles segments m = wid, wid+4, ...

    // ---- Stage this batch's operands into shared (float4, coalesced) ----
    {
        const float4* s1 = reinterpret_cast<const float4*>(x1 + (size_t)b * NMDIM * CDIM);
        const float4* s2 = reinterpret_cast<const float4*>(x2 + (size_t)b * NMDIM * CDIM);
        const float4* sw = reinterpret_cast<const float4*>(w  + (size_t)b * NWDIM * CDIM);
        float4* d = reinterpret_cast<float4*>(sm);
        const int N1  = NMDIM * CDIM / 4;   // 400
        const int NWq = NWDIM * CDIM / 4;   // 880
        for (int i = tid; i < N1;  i += 128) d[i]          = s1[i];
        for (int i = tid; i < N1;  i += 128) d[N1 + i]     = s2[i];
        for (int i = tid; i < NWq; i += 128) d[2 * N1 + i] = sw[i];
    }
    __syncthreads();

    // Per-lane base; dynamic index -> one IADD per operand (byte offsets).
    const char* base = reinterpret_cast<const char*>(sm) + lid * 8;
    char* outb = reinterpret_cast<char*>(out + (size_t)b * NMDIM * CDIM) + lid * 8;

    // Segment loop: branch-free inner body, fully pipelineable.
    for (int m = wid; m < NMDIM; m += 4) {
        const int n0 = g_ptr[m];
        const int n1 = g_ptr[m + 1];
        unsigned long long acc = 0ULL;   // packed float2 accumulator

        #pragma unroll 8
        for (int n = n0; n < n1; ++n) {
            const int4 e = g_off[n];     // one LDG.128, uniform, L1-hit
            const unsigned long long v1 =
                *reinterpret_cast<const unsigned long long*>(base + e.x);  // LDS.64
            const unsigned long long v2 =
                *reinterpret_cast<const unsigned long long*>(base + e.y);  // LDS.64
            const unsigned long long vw =
                *reinterpret_cast<const unsigned long long*>(base + e.z);  // LDS.64
            acc = fma_f32x2(mul_f32x2(v1, v2),
                            mul_f32x2(vw, bcast_f32x2(__int_as_float(e.w))),
                            acc);
        }
        // Empty segments naturally write 0 (d_out is poisoned; must be written).
        *reinterpret_cast<unsigned long long*>(outb + m * ROWB) = acc;
    }
}

extern "C" void kernel_launch(void* const* d_in, const int* in_sizes, int n_in,
                              void* d_out, int out_size) {
    // metadata order == reference signature order:
    // x1, x2, weight, CG_vals, M_out, M1, M2, l_ind
    const float* x1    = (const float*)d_in[0];
    const float* x2    = (const float*)d_in[1];
    const float* wt    = (const float*)d_in[2];
    const float* cg    = (const float*)d_in[3];
    const int*   M_out = (const int*)d_in[4];
    const int*   M1    = (const int*)d_in[5];
    const int*   M2    = (const int*)d_in[6];
    const int*   l_ind = (const int*)d_in[7];

    const int nnz = in_sizes[3];
    const int B   = in_sizes[0] / (NMDIM * CDIM);

    pack_idx_kernel<<<(nnz + 255) / 256, 256>>>(M1, M2, l_ind, M_out, cg, nnz);
    wtp_kernel<<<B, 128>>>(x1, x2, wt, (float*)d_out, nnz);
}